// round 12
// baseline (speedup 1.0000x reference)
#include <cuda_runtime.h>
#include <cuda_bf16.h>
#include <cuda_fp16.h>
#include <math.h>
#include <stdint.h>

#define BATCH 8
#define SEQ   1315
#define DIMIN 512
#define NOUTC 1536
#define NH    8
#define HD    64
#define NIMG  291
#define NGENE 1024
#define KW    33
#define KPAD  16
#define QK_SCALE 0.125f

// scratch (allocation-free rule: __device__ globals)
__device__ float g_V [BATCH*NH*SEQ*HD];                 // f32 V for resid conv
__device__ __half g_Qh[BATCH*NH*SEQ*HD];
__device__ __half g_Kh[BATCH*NH*SEQ*HD];
__device__ __half g_Vh[BATCH*NH*SEQ*HD];
__device__ __nv_bfloat16 g_Wth[NOUTC*DIMIN];   // [n][k] bf16 hi
__device__ __nv_bfloat16 g_Wtl[NOUTC*DIMIN];   // [n][k] bf16 lo

__device__ __forceinline__ uint32_t smem_u32(const void* p) {
    uint32_t a;
    asm("{ .reg .u64 t; cvta.to.shared.u64 t, %1; cvt.u32.u64 %0, t; }"
        : "=r"(a) : "l"(p));
    return a;
}
__device__ __forceinline__ void bsplit(float x, __nv_bfloat16& h, __nv_bfloat16& l) {
    h = __float2bfloat16(x);
    l = __float2bfloat16(x - __bfloat162float(h));
}
__device__ __forceinline__ unsigned packbf2(__nv_bfloat16 a, __nv_bfloat16 b) {
    __nv_bfloat162 t(a, b);
    return *(unsigned*)&t;
}
__device__ __forceinline__ unsigned packh2(__half a, __half b) {
    __half2 t = __halves2half2(a, b);
    return *(unsigned*)&t;
}

// ---------------------------------------------------------------------------
// prep: W[512][1536] f32 -> Wth/Wtl[1536][512] bf16 (transpose + split)
// ---------------------------------------------------------------------------
__global__ void prep_w_kernel(const float* __restrict__ W)
{
    __shared__ float t[32][33];
    const int n0 = blockIdx.x * 32, k0 = blockIdx.y * 32;
    const int tx = threadIdx.x, ty = threadIdx.y;
#pragma unroll
    for (int r = 0; r < 4; r++)
        t[ty + 8 * r][tx] = W[(k0 + ty + 8 * r) * NOUTC + n0 + tx];
    __syncthreads();
#pragma unroll
    for (int r = 0; r < 4; r++) {
        float v = t[tx][ty + 8 * r];
        __nv_bfloat16 h, l;
        bsplit(v, h, l);
        int o = (n0 + ty + 8 * r) * DIMIN + k0 + tx;
        g_Wth[o] = h;
        g_Wtl[o] = l;
    }
}

// ---------------------------------------------------------------------------
// common MMA helpers
// ---------------------------------------------------------------------------
__device__ __forceinline__ void ldmx4(unsigned& r0, unsigned& r1, unsigned& r2,
                                      unsigned& r3, uint32_t addr) {
    asm volatile("ldmatrix.sync.aligned.m8n8.x4.shared.b16 {%0,%1,%2,%3}, [%4];"
                 : "=r"(r0), "=r"(r1), "=r"(r2), "=r"(r3) : "r"(addr));
}
__device__ __forceinline__ void ldmx4t(unsigned& r0, unsigned& r1, unsigned& r2,
                                       unsigned& r3, uint32_t addr) {
    asm volatile("ldmatrix.sync.aligned.m8n8.x4.trans.shared.b16 {%0,%1,%2,%3}, [%4];"
                 : "=r"(r0), "=r"(r1), "=r"(r2), "=r"(r3) : "r"(addr));
}
__device__ __forceinline__ void mma_bf(float d[4], unsigned a0, unsigned a1,
                                       unsigned a2, unsigned a3,
                                       unsigned b0, unsigned b1) {
    asm volatile(
        "mma.sync.aligned.m16n8k16.row.col.f32.bf16.bf16.f32 "
        "{%0,%1,%2,%3}, {%4,%5,%6,%7}, {%8,%9}, {%0,%1,%2,%3};"
        : "+f"(d[0]), "+f"(d[1]), "+f"(d[2]), "+f"(d[3])
        : "r"(a0), "r"(a1), "r"(a2), "r"(a3), "r"(b0), "r"(b1));
}
__device__ __forceinline__ void mma_f16(float d[4], const unsigned a[4],
                                        unsigned b0, unsigned b1) {
    asm volatile(
        "mma.sync.aligned.m16n8k16.row.col.f32.f16.f16.f32 "
        "{%0,%1,%2,%3}, {%4,%5,%6,%7}, {%8,%9}, {%0,%1,%2,%3};"
        : "+f"(d[0]), "+f"(d[1]), "+f"(d[2]), "+f"(d[3])
        : "r"(a[0]), "r"(a[1]), "r"(a[2]), "r"(a[3]), "r"(b0), "r"(b1));
}
#define CP16(dst, src) \
    asm volatile("cp.async.ca.shared.global [%0], [%1], 16;" :: "r"(dst), "l"(src))
#define CP_COMMIT() asm volatile("cp.async.commit_group;" ::: "memory")
#define CP_WAIT(n)  asm volatile("cp.async.wait_group %0;" :: "n"(n) : "memory")

// ---------------------------------------------------------------------------
// QKV GEMM via mma.sync m16n8k16 bf16x3. CTA 128x128, warp tile 64x32.
// epilogue: Q/K/V -> fp16 hi; V also f32 (for resid)
// ---------------------------------------------------------------------------
#define AST 40
#define STG 40960

__global__ __launch_bounds__(256)
void qkv_gemm_mma(const float* __restrict__ X)
{
    extern __shared__ __align__(16) char smraw[];
    const int tid = threadIdx.x;
    const int wid = tid >> 5, lane = tid & 31;
    const int row0 = blockIdx.x * 128;
    const int col0 = blockIdx.y * 128;
    const int M = BATCH * SEQ;
    const int wm = wid >> 2, wn = wid & 3;
    const int m_base = wm * 64, n_base = wn * 32;

    const uint32_t sbase = smem_u32(smraw);
    const uint32_t aoff = ((m_base + (lane & 15)) * AST + (lane >> 4) * 8) * 2;
    const uint32_t boff = ((n_base + (lane >> 4) * 8 + (lane & 7)) * AST
                           + ((lane >> 3) & 1) * 8) * 2;

    float d[4][4][4];
#pragma unroll
    for (int i = 0; i < 4; i++)
#pragma unroll
        for (int j = 0; j < 4; j++)
#pragma unroll
            for (int c = 0; c < 4; c++) d[i][j][c] = 0.f;

    float4 xa[4]; uint2 wh4[4], wl4[4];

    auto load_chunk = [&](int kc) {
        const int k0 = kc * 32;
#pragma unroll
        for (int it = 0; it < 4; it++) {
            int idx = tid + it * 256;
            int r = idx >> 3, c4 = (idx & 7) * 4;
            int gr = row0 + r; if (gr >= M) gr = M - 1;
            xa[it]  = *(const float4*)(X + gr * DIMIN + k0 + c4);
            wh4[it] = *(const uint2*)(g_Wth + (col0 + r) * DIMIN + k0 + c4);
            wl4[it] = *(const uint2*)(g_Wtl + (col0 + r) * DIMIN + k0 + c4);
        }
    };
    auto store_stage = [&](int s) {
        char* st = smraw + s * STG;
#pragma unroll
        for (int it = 0; it < 4; it++) {
            int idx = tid + it * 256;
            int r = idx >> 3, c4 = (idx & 7) * 4;
            int off = (r * AST + c4) * 2;
            __nv_bfloat16 h0, l0, h1, l1, h2, l2, h3, l3;
            bsplit(xa[it].x, h0, l0); bsplit(xa[it].y, h1, l1);
            bsplit(xa[it].z, h2, l2); bsplit(xa[it].w, h3, l3);
            uint2 ah; ah.x = packbf2(h0, h1); ah.y = packbf2(h2, h3);
            uint2 al; al.x = packbf2(l0, l1); al.y = packbf2(l2, l3);
            *(uint2*)(st + off)             = ah;
            *(uint2*)(st + 10240 + off)     = al;
            *(uint2*)(st + 20480 + off)     = wh4[it];
            *(uint2*)(st + 30720 + off)     = wl4[it];
        }
    };

    load_chunk(0);
    store_stage(0);
    __syncthreads();

    for (int kc = 0; kc < 16; kc++) {
        const int cur = kc & 1;
        const bool more = (kc < 15);
        if (more) load_chunk(kc + 1);

        const uint32_t stg = sbase + cur * STG;
#pragma unroll
        for (int kk = 0; kk < 2; kk++) {
            const uint32_t kkb = kk * 32;
            unsigned bh[4][2], bl[4][2];
            ldmx4(bh[0][0], bh[0][1], bh[1][0], bh[1][1], stg + 20480 + boff + kkb);
            ldmx4(bh[2][0], bh[2][1], bh[3][0], bh[3][1], stg + 20480 + boff + kkb + 16 * AST * 2);
            ldmx4(bl[0][0], bl[0][1], bl[1][0], bl[1][1], stg + 30720 + boff + kkb);
            ldmx4(bl[2][0], bl[2][1], bl[3][0], bl[3][1], stg + 30720 + boff + kkb + 16 * AST * 2);
#pragma unroll
            for (int mi = 0; mi < 4; mi++) {
                unsigned a0, a1, a2, a3, l0, l1, l2, l3;
                ldmx4(a0, a1, a2, a3, stg + aoff + kkb + mi * 16 * AST * 2);
                ldmx4(l0, l1, l2, l3, stg + 10240 + aoff + kkb + mi * 16 * AST * 2);
#pragma unroll
                for (int ni = 0; ni < 4; ni++) {
                    mma_bf(d[mi][ni], a0, a1, a2, a3, bh[ni][0], bh[ni][1]);
                    mma_bf(d[mi][ni], a0, a1, a2, a3, bl[ni][0], bl[ni][1]);
                    mma_bf(d[mi][ni], l0, l1, l2, l3, bh[ni][0], bh[ni][1]);
                }
            }
        }
        if (more) {
            store_stage(cur ^ 1);
            __syncthreads();
        }
    }

    // epilogue: Q/K/V hi fp16; V also f32
    const int gid = lane >> 2, tq = lane & 3;
#pragma unroll
    for (int mi = 0; mi < 4; mi++) {
#pragma unroll
        for (int ni = 0; ni < 4; ni++) {
            int gc = col0 + n_base + ni * 8 + tq * 2;
            int which = gc >> 9;
            int hh = (gc >> 6) & 7;
            int dd = gc & 63;
            float sc = (which == 0) ? QK_SCALE : 1.f;
            __half* dh = (which == 0) ? g_Qh : (which == 1) ? g_Kh : g_Vh;
#pragma unroll
            for (int hrow = 0; hrow < 2; hrow++) {
                int m = row0 + m_base + mi * 16 + gid + hrow * 8;
                if (m >= M) continue;
                int bb = m / SEQ, pos = m % SEQ;
                int idx = ((bb * NH + hh) * SEQ + pos) * HD + dd;
                float f0 = d[mi][ni][hrow * 2 + 0] * sc;
                float f1 = d[mi][ni][hrow * 2 + 1] * sc;
                *(unsigned*)(dh + idx) = packh2(__float2half_rn(f0),
                                                __float2half_rn(f1));
                if (which == 2) {
                    float2 v; v.x = f0; v.y = f1;
                    *(float2*)(g_V + idx) = v;
                }
            }
        }
    }
}

// ---------------------------------------------------------------------------
// Fused attention on mma.sync, flash-style.
// Q,K,V: fp16 hi; P: fp16 hi. S = qh*kh ; O += ph*vh (1 MMA-set each)
// CTA = 128 threads (4 warps), q-tile 64, k-tile 64, 2-stage cp.async.
// ---------------------------------------------------------------------------
#define ATT_ST 72            // halves per smem row
#define T_ROW (64 * ATT_ST)  // 4608 halves per 64x64 tile
#define STG0_OFF T_ROW
#define STGSZ (2 * T_ROW)    // Kh | Vh

struct TileD { int kor; int vb; int nk; int mode; bool wrap; };
// mode: 0 = STATS (gene keys), 1 = inner-softmax probs, 2 = RAW

__device__ __forceinline__ TileD tdesc(bool is_img, int t) {
    TileD td;
    if (!is_img) {
        td.kor = t * 64;
        td.nk  = (SEQ - td.kor) < 64 ? (SEQ - td.kor) : 64;
        td.vb  = td.kor + NGENE;
        td.mode = 2; td.wrap = true;
    } else if (t < 16) {
        td.kor = NIMG + t * 64; td.nk = 64; td.vb = 0; td.mode = 0; td.wrap = false;
    } else if (t < 32) {
        td.kor = NIMG + (t - 16) * 64; td.nk = 64; td.vb = (t - 16) * 64;
        td.mode = 1; td.wrap = false;
    } else {
        td.kor = (t - 32) * 64;
        td.nk  = (NIMG - td.kor) < 64 ? (NIMG - td.kor) : 64;
        td.vb  = td.kor + NGENE;
        td.mode = 2; td.wrap = false;
    }
    return td;
}

__global__ __launch_bounds__(128)
void attn_mma(float* __restrict__ out)
{
    extern __shared__ __align__(16) __half smh[];
    const int tid = threadIdx.x;
    const int lane = tid & 31, wid = tid >> 5;
    const int tq = lane & 3;
    const int bh = blockIdx.x, qt = blockIdx.y;
    const int bhoff = bh * SEQ * HD;

    const bool is_img = (qt >= 16);
    int qorig0, tbase, nq;
    if (!is_img) { qorig0 = NIMG + qt * 64; tbase = qt * 64; nq = 64; }
    else {
        int i0 = (qt - 16) * 64;
        qorig0 = i0; tbase = NGENE + i0;
        nq = NIMG - i0; if (nq > 64) nq = 64;
    }
    const int ntiles = is_img ? 37 : 21;
    const uint32_t sb = smem_u32(smh);

    // ---- issue Q tile (Qh) via cp.async ----
#pragma unroll
    for (int i = 0; i < 4; i++) {
        int id = tid + i * 128;
        int row = id >> 3, c8 = (id & 7) * 8;
        int tok = qorig0 + (row < nq ? row : nq - 1);
        const __half* src = g_Qh + bhoff + tok * HD + c8;
        uint32_t dst = sb + (row * ATT_ST + c8) * 2;
        CP16(dst, src);
    }
    CP_COMMIT();

    auto issue_kv = [&](int t, int s) {
        TileD td = tdesc(is_img, t);
        uint32_t stg = sb + (STG0_OFF + s * STGSZ) * 2;
#pragma unroll
        for (int i = 0; i < 8; i++) {
            int id = tid + i * 128;
            int arr = id >> 9, rem = id & 511;   // 0 = Kh, 1 = Vh
            int row = rem >> 3, c8 = (rem & 7) * 8;
            int rc = row < td.nk ? row : td.nk - 1;
            const __half* src;
            if (arr == 0) {
                src = g_Kh + bhoff + (td.kor + rc) * HD + c8;
            } else {
                int vi = td.vb + rc;
                if (td.wrap && vi >= SEQ) vi -= SEQ;
                src = g_Vh + bhoff + vi * HD + c8;
            }
            uint32_t dst = stg + (arr * T_ROW + row * ATT_ST + c8) * 2;
            CP16(dst, src);
        }
        CP_COMMIT();
    };

    issue_kv(0, 0);
    CP_WAIT(1);            // Q done (stage0 may be in flight)
    __syncthreads();

    // ---- Q A-fragments (held in regs for the whole kernel) ----
    const int wm = wid;    // warp m-tile
    unsigned qa_h[4][4];
    {
        uint32_t aoff = sb + (((wm * 16 + (lane & 15)) * ATT_ST + (lane >> 4) * 8)) * 2;
#pragma unroll
        for (int c = 0; c < 4; c++)
            ldmx4(qa_h[c][0], qa_h[c][1], qa_h[c][2], qa_h[c][3], aoff + c * 32);
    }

    float O[8][4];
#pragma unroll
    for (int j = 0; j < 8; j++)
#pragma unroll
        for (int c = 0; c < 4; c++) O[j][c] = 0.f;
    float m0 = -INFINITY, m1 = -INFINITY, l0 = 0.f, l1 = 0.f;
    float mg0 = -INFINITY, mg1 = -INFINITY, lg0 = 0.f, lg1 = 0.f;
    float ivl0 = 0.f, ivl1 = 0.f;

    // per-lane ldmatrix address components
    const uint32_t krow = (lane >> 4) * 8 + (lane & 7);       // for K (n-rows)
    const uint32_t ksel = ((lane >> 3) & 1) * 8;              // k halves
    const uint32_t vrow = ((lane >> 3) & 1) * 8 + (lane & 7); // for V (k-rows)
    const uint32_t vcol = (lane >> 4) * 8;

    for (int t = 0; t < ntiles; t++) {
        const int cur = t & 1;
        const bool more = (t + 1 < ntiles);
        TileD td = tdesc(is_img, t);
        if (more) issue_kv(t + 1, cur ^ 1);
        if (more) CP_WAIT(1); else CP_WAIT(0);
        __syncthreads();

        const uint32_t stg = sb + (STG0_OFF + cur * STGSZ) * 2;

        // ---- S = Q K^T (1-term: qh*kh) ----
        float S[8][4];
#pragma unroll
        for (int j = 0; j < 8; j++)
#pragma unroll
            for (int c = 0; c < 4; c++) S[j][c] = 0.f;
#pragma unroll
        for (int jj = 0; jj < 4; jj++) {
            uint32_t rb = (jj * 16 + krow) * ATT_ST;
#pragma unroll
            for (int c = 0; c < 4; c++) {
                uint32_t ad = stg + ((rb + c * 16 + ksel)) * 2;
                unsigned b0, b1, b2, b3;
                ldmx4(b0, b1, b2, b3, ad);                    // Kh
                mma_f16(S[2*jj],   qa_h[c], b0, b1);
                mma_f16(S[2*jj+1], qa_h[c], b2, b3);
            }
        }

        if (td.mode == 0) {
            // inner-softmax stats over gene keys (rows: r0=lane>>2, r1=r0+8)
            float tm0 = -INFINITY, tm1 = -INFINITY;
#pragma unroll
            for (int j = 0; j < 8; j++) {
                tm0 = fmaxf(tm0, fmaxf(S[j][0], S[j][1]));
                tm1 = fmaxf(tm1, fmaxf(S[j][2], S[j][3]));
            }
            tm0 = fmaxf(tm0, __shfl_xor_sync(0xffffffffu, tm0, 1));
            tm0 = fmaxf(tm0, __shfl_xor_sync(0xffffffffu, tm0, 2));
            tm1 = fmaxf(tm1, __shfl_xor_sync(0xffffffffu, tm1, 1));
            tm1 = fmaxf(tm1, __shfl_xor_sync(0xffffffffu, tm1, 2));
            float mn0 = fmaxf(mg0, tm0), mn1 = fmaxf(mg1, tm1);
            float rs0 = 0.f, rs1 = 0.f;
#pragma unroll
            for (int j = 0; j < 8; j++) {
                rs0 += __expf(S[j][0] - mn0) + __expf(S[j][1] - mn0);
                rs1 += __expf(S[j][2] - mn1) + __expf(S[j][3] - mn1);
            }
            rs0 += __shfl_xor_sync(0xffffffffu, rs0, 1);
            rs0 += __shfl_xor_sync(0xffffffffu, rs0, 2);
            rs1 += __shfl_xor_sync(0xffffffffu, rs1, 1);
            rs1 += __shfl_xor_sync(0xffffffffu, rs1, 2);
            lg0 = lg0 * __expf(mg0 - mn0) + rs0; mg0 = mn0;
            lg1 = lg1 * __expf(mg1 - mn1) + rs1; mg1 = mn1;
        } else {
            if (is_img && t == 16) { ivl0 = 1.f / lg0; ivl1 = 1.f / lg1; }
            if (td.mode == 1) {
#pragma unroll
                for (int j = 0; j < 8; j++) {
                    S[j][0] = __expf(S[j][0] - mg0) * ivl0;
                    S[j][1] = __expf(S[j][1] - mg0) * ivl0;
                    S[j][2] = __expf(S[j][2] - mg1) * ivl1;
                    S[j][3] = __expf(S[j][3] - mg1) * ivl1;
                }
            } else if (td.nk < 64) {
#pragma unroll
                for (int j = 0; j < 8; j++) {
                    int c0 = j * 8 + tq * 2;
                    if (c0     >= td.nk) { S[j][0] = -INFINITY; S[j][2] = -INFINITY; }
                    if (c0 + 1 >= td.nk) { S[j][1] = -INFINITY; S[j][3] = -INFINITY; }
                }
            }
            // online softmax
            float tm0 = -INFINITY, tm1 = -INFINITY;
#pragma unroll
            for (int j = 0; j < 8; j++) {
                tm0 = fmaxf(tm0, fmaxf(S[j][0], S[j][1]));
                tm1 = fmaxf(tm1, fmaxf(S[j][2], S[j][3]));
            }
            tm0 = fmaxf(tm0, __shfl_xor_sync(0xffffffffu, tm0, 1));
            tm0 = fmaxf(tm0, __shfl_xor_sync(0xffffffffu, tm0, 2));
            tm1 = fmaxf(tm1, __shfl_xor_sync(0xffffffffu, tm1, 1));
            tm1 = fmaxf(tm1, __shfl_xor_sync(0xffffffffu, tm1, 2));
            float mn0 = fmaxf(m0, tm0), mn1 = fmaxf(m1, tm1);
            float sc0 = __expf(m0 - mn0), sc1 = __expf(m1 - mn1);
            float rs0 = 0.f, rs1 = 0.f;
#pragma unroll
            for (int j = 0; j < 8; j++) {
                S[j][0] = __expf(S[j][0] - mn0); rs0 += S[j][0];
                S[j][1] = __expf(S[j][1] - mn0); rs0 += S[j][1];
                S[j][2] = __expf(S[j][2] - mn1); rs1 += S[j][2];
                S[j][3] = __expf(S[j][3] - mn1); rs1 += S[j][3];
            }
            rs0 += __shfl_xor_sync(0xffffffffu, rs0, 1);
            rs0 += __shfl_xor_sync(0xffffffffu, rs0, 2);
            rs1 += __shfl_xor_sync(0xffffffffu, rs1, 1);
            rs1 += __shfl_xor_sync(0xffffffffu, rs1, 2);
            l0 = l0 * sc0 + rs0; m0 = mn0;
            l1 = l1 * sc1 + rs1; m1 = mn1;
#pragma unroll
            for (int j = 0; j < 8; j++) {
                O[j][0] *= sc0; O[j][1] *= sc0;
                O[j][2] *= sc1; O[j][3] *= sc1;
            }
            // P fragments (A, m16k16): hi only; emitted directly in
            // {a0,a1,a2,a3} = {(r0,k0),(r0+8,k0),(r0,k8),(r0+8,k8)} order.
            unsigned pha[4][4];
#pragma unroll
            for (int kk = 0; kk < 4; kk++) {
#pragma unroll
                for (int q = 0; q < 4; q++) {
                    int j = 2 * kk + (q >> 1);
                    int i0 = (q & 1) ? 2 : 0;
                    pha[kk][q] = packh2(__float2half_rn(S[j][i0]),
                                        __float2half_rn(S[j][i0 + 1]));
                }
            }
            // ---- O += P V (1-term: ph*vh) ----
#pragma unroll
            for (int kk = 0; kk < 4; kk++) {
                uint32_t rb = (kk * 16 + vrow) * ATT_ST + vcol;
#pragma unroll
                for (int dp = 0; dp < 4; dp++) {
                    uint32_t ad = stg + (T_ROW + rb + dp * 16) * 2;
                    unsigned v0, v1, v2, v3;
                    ldmx4t(v0, v1, v2, v3, ad);               // Vh
                    mma_f16(O[2*dp],   pha[kk], v0, v1);
                    mma_f16(O[2*dp+1], pha[kk], v2, v3);
                }
            }
        }
        __syncthreads();
    }

    // ---- epilogue ----
    const int bb = bh >> 3, hh = bh & 7;
    const int r0 = wm * 16 + (lane >> 2), r1 = r0 + 8;
    float inv0 = 1.f / l0, inv1 = 1.f / l1;
#pragma unroll
    for (int dj = 0; dj < 8; dj++) {
        int d0 = dj * 8 + tq * 2;
        if (r0 < nq) {
            float2 o; o.x = O[dj][0] * inv0; o.y = O[dj][1] * inv0;
            *(float2*)(out + ((long)(bb * SEQ + tbase + r0) * (NH * HD)) + hh * HD + d0) = o;
        }
        if (r1 < nq) {
            float2 o; o.x = O[dj][2] * inv1; o.y = O[dj][3] * inv1;
            *(float2*)(out + ((long)(bb * SEQ + tbase + r1) * (NH * HD)) + hh * HD + d0) = o;
        }
    }
}

// ---------------------------------------------------------------------------
// Kernel 3: depthwise conv residual, strips of 8
// ---------------------------------------------------------------------------
#define NSB 42

__global__ __launch_bounds__(256)
void resid_kernel(const float* __restrict__ wres, float* __restrict__ out)
{
    const int blk = blockIdx.x;
    const int sb = blk % NSB;
    const int bh = blk / NSB;
    const int bb = bh >> 3, hh = bh & 7;
    const int dd = threadIdx.x & 63;
    const int s = sb * 4 + (threadIdx.x >> 6);
    const int t0 = s * 8;
    if (t0 >= SEQ) return;

    const float* __restrict__ v = g_V + ((bb * NH + hh) * SEQ) * HD + dd;
    const float* __restrict__ w = wres + hh * KW;

    float win[40];
#pragma unroll
    for (int i = 0; i < 40; i++) {
        int p = t0 - KPAD + i;
        win[i] = (p >= 0 && p < SEQ) ? v[p * HD] : 0.f;
    }
    float o[8];
#pragma unroll
    for (int i = 0; i < 8; i++) o[i] = 0.f;
#pragma unroll
    for (int k = 0; k < KW; k++) {
        float wk = __ldg(w + k);
#pragma unroll
        for (int i = 0; i < 8; i++) o[i] += wk * win[i + k];
    }
#pragma unroll
    for (int i = 0; i < 8; i++) {
        int t = t0 + i;
        if (t < SEQ) {
            int oi = (bb * SEQ + t) * (NH * HD) + hh * HD + dd;
            out[oi] += o[i];
        }
    }
}

// ---------------------------------------------------------------------------
extern "C" void kernel_launch(void* const* d_in, const int* in_sizes, int n_in,
                              void* d_out, int out_size)
{
    const float* x     = (const float*)d_in[0];
    const float* w_qkv = (const float*)d_in[1];
    const float* w_res = (const float*)d_in[2];
    float* out = (float*)d_out;

    const int gemm_smem = 2 * STG;                            // 81920 B
    cudaFuncSetAttribute(qkv_gemm_mma, cudaFuncAttributeMaxDynamicSharedMemorySize, gemm_smem);
    const int attn_smem = (T_ROW + 2 * STGSZ) * 2;            // 46080 B
    cudaFuncSetAttribute(attn_mma, cudaFuncAttributeMaxDynamicSharedMemorySize, attn_smem);

    dim3 gp(NOUTC / 32, DIMIN / 32);
    prep_w_kernel<<<gp, dim3(32, 8)>>>(w_qkv);

    dim3 g1((BATCH * SEQ + 127) / 128, NOUTC / 128);
    qkv_gemm_mma<<<g1, 256, gemm_smem>>>(x);

    dim3 g2(BATCH * NH, 21);
    attn_mma<<<g2, 128, attn_smem>>>(out);

    resid_kernel<<<BATCH * NH * NSB, 256>>>(w_res, out);
}

// round 13
// speedup vs baseline: 1.2103x; 1.2103x over previous
#include <cuda_runtime.h>
#include <cuda_fp16.h>
#include <math.h>
#include <stdint.h>

#define BATCH 8
#define SEQ   1315
#define DIMIN 512
#define NOUTC 1536
#define NH    8
#define HD    64
#define NIMG  291
#define NGENE 1024
#define KW    33
#define KPAD  16
#define QK_SCALE 0.125f

// scratch (allocation-free rule: __device__ globals)
__device__ float g_V [BATCH*NH*SEQ*HD];                 // f32 V for resid conv
__device__ __half g_Qh[BATCH*NH*SEQ*HD];
__device__ __half g_Kh[BATCH*NH*SEQ*HD];
__device__ __half g_Vh[BATCH*NH*SEQ*HD];
__device__ __half g_Xh[BATCH*SEQ*DIMIN], g_Xl[BATCH*SEQ*DIMIN];  // [m][k]
__device__ __half g_Wh[NOUTC*DIMIN];                    // [n][k] fp16

__device__ __forceinline__ uint32_t smem_u32(const void* p) {
    uint32_t a;
    asm("{ .reg .u64 t; cvta.to.shared.u64 t, %1; cvt.u32.u64 %0, t; }"
        : "=r"(a) : "l"(p));
    return a;
}
__device__ __forceinline__ unsigned packh2(__half a, __half b) {
    __half2 t = __halves2half2(a, b);
    return *(unsigned*)&t;
}

// ---------------------------------------------------------------------------
// prep_x: X f32 -> Xh, Xl fp16 (hi/lo split), row-major [m][k]
// ---------------------------------------------------------------------------
__global__ __launch_bounds__(256)
void prep_x_kernel(const float* __restrict__ X)
{
    int i = (blockIdx.x * 256 + threadIdx.x) * 4;
    if (i >= BATCH * SEQ * DIMIN) return;
    float4 v = *(const float4*)(X + i);
    __half h0 = __float2half_rn(v.x), h1 = __float2half_rn(v.y);
    __half h2 = __float2half_rn(v.z), h3 = __float2half_rn(v.w);
    uint2 ph; ph.x = packh2(h0, h1); ph.y = packh2(h2, h3);
    uint2 pl;
    pl.x = packh2(__float2half_rn(v.x - __half2float(h0)),
                  __float2half_rn(v.y - __half2float(h1)));
    pl.y = packh2(__float2half_rn(v.z - __half2float(h2)),
                  __float2half_rn(v.w - __half2float(h3)));
    *(uint2*)(g_Xh + i) = ph;
    *(uint2*)(g_Xl + i) = pl;
}

// ---------------------------------------------------------------------------
// prep_w: W[512][1536] f32 -> Wh[1536][512] fp16 (transpose)
// ---------------------------------------------------------------------------
__global__ void prep_w_kernel(const float* __restrict__ W)
{
    __shared__ float t[32][33];
    const int n0 = blockIdx.x * 32, k0 = blockIdx.y * 32;
    const int tx = threadIdx.x, ty = threadIdx.y;
#pragma unroll
    for (int r = 0; r < 4; r++)
        t[ty + 8 * r][tx] = W[(k0 + ty + 8 * r) * NOUTC + n0 + tx];
    __syncthreads();
#pragma unroll
    for (int r = 0; r < 4; r++)
        g_Wh[(n0 + ty + 8 * r) * DIMIN + k0 + tx] =
            __float2half_rn(t[tx][ty + 8 * r]);
}

// ---------------------------------------------------------------------------
// common MMA helpers
// ---------------------------------------------------------------------------
__device__ __forceinline__ void ldmx4(unsigned& r0, unsigned& r1, unsigned& r2,
                                      unsigned& r3, uint32_t addr) {
    asm volatile("ldmatrix.sync.aligned.m8n8.x4.shared.b16 {%0,%1,%2,%3}, [%4];"
                 : "=r"(r0), "=r"(r1), "=r"(r2), "=r"(r3) : "r"(addr));
}
__device__ __forceinline__ void ldmx4t(unsigned& r0, unsigned& r1, unsigned& r2,
                                       unsigned& r3, uint32_t addr) {
    asm volatile("ldmatrix.sync.aligned.m8n8.x4.trans.shared.b16 {%0,%1,%2,%3}, [%4];"
                 : "=r"(r0), "=r"(r1), "=r"(r2), "=r"(r3) : "r"(addr));
}
__device__ __forceinline__ void mma_f16(float d[4], const unsigned a[4],
                                        unsigned b0, unsigned b1) {
    asm volatile(
        "mma.sync.aligned.m16n8k16.row.col.f32.f16.f16.f32 "
        "{%0,%1,%2,%3}, {%4,%5,%6,%7}, {%8,%9}, {%0,%1,%2,%3};"
        : "+f"(d[0]), "+f"(d[1]), "+f"(d[2]), "+f"(d[3])
        : "r"(a[0]), "r"(a[1]), "r"(a[2]), "r"(a[3]), "r"(b0), "r"(b1));
}
#define CP16(dst, src) \
    asm volatile("cp.async.ca.shared.global [%0], [%1], 16;" :: "r"(dst), "l"(src))
#define CP_COMMIT() asm volatile("cp.async.commit_group;" ::: "memory")
#define CP_WAIT(n)  asm volatile("cp.async.wait_group %0;" :: "n"(n) : "memory")

// ---------------------------------------------------------------------------
// QKV GEMM: mma.sync m16n8k16 fp16 2-term (xh*wh + xl*wh).
// CTA 128x128, 8 warps (2m x 4n), warp tile 64x32, K-chunks of 32.
// smem/stage: Ah | Al | Bh, each 128x32 fp16 stride-40. Pure cp.async feed.
// epilogue: Q/K/V -> fp16; V also f32 (for resid)
// ---------------------------------------------------------------------------
#define GAST 40
#define GT_ROW (128 * GAST)          // halves per tile (5120)
#define GSTG (3 * GT_ROW)            // halves per stage (15360)

__global__ __launch_bounds__(256)
void qkv_gemm_mma(const float* __restrict__ X_unused)
{
    extern __shared__ __align__(16) __half smg[];
    const int tid = threadIdx.x;
    const int wid = tid >> 5, lane = tid & 31;
    const int row0 = blockIdx.x * 128;
    const int col0 = blockIdx.y * 128;
    const int M = BATCH * SEQ;
    const int wm = wid >> 2, wn = wid & 3;
    const int m_base = wm * 64, n_base = wn * 32;

    const uint32_t sb = smem_u32(smg);
    const uint32_t aoff = ((m_base + (lane & 15)) * GAST + (lane >> 4) * 8) * 2;
    const uint32_t boff = ((n_base + (lane >> 4) * 8 + (lane & 7)) * GAST
                           + ((lane >> 3) & 1) * 8) * 2;

    float d[4][4][4];
#pragma unroll
    for (int i = 0; i < 4; i++)
#pragma unroll
        for (int j = 0; j < 4; j++)
#pragma unroll
            for (int c = 0; c < 4; c++) d[i][j][c] = 0.f;

    auto issue_stage = [&](int s, int kc) {
        const int k0 = kc * 32;
        uint32_t stg = sb + s * GSTG * 2;
#pragma unroll
        for (int i = 0; i < 6; i++) {
            int id = tid + i * 256;
            int arr = id >> 9, rem = id & 511;   // 0:Ah 1:Al 2:Bh
            int row = rem >> 2, c8 = (rem & 3) * 8;
            const __half* src;
            if (arr == 2) {
                src = g_Wh + (col0 + row) * DIMIN + k0 + c8;
            } else {
                int gr = row0 + row; if (gr >= M) gr = M - 1;
                src = (arr ? g_Xl : g_Xh) + gr * DIMIN + k0 + c8;
            }
            uint32_t dst = stg + (arr * GT_ROW + row * GAST + c8) * 2;
            CP16(dst, src);
        }
        CP_COMMIT();
    };

    issue_stage(0, 0);

    for (int kc = 0; kc < 16; kc++) {
        const int cur = kc & 1;
        const bool more = (kc < 15);
        if (more) issue_stage(cur ^ 1, kc + 1);
        if (more) CP_WAIT(1); else CP_WAIT(0);
        __syncthreads();

        const uint32_t stg = sb + cur * GSTG * 2;
#pragma unroll
        for (int kk = 0; kk < 2; kk++) {
            const uint32_t kkb = kk * 32;        // 16 halves
            unsigned bh[4][2];
            ldmx4(bh[0][0], bh[0][1], bh[1][0], bh[1][1],
                  stg + 2 * GT_ROW * 2 + boff + kkb);
            ldmx4(bh[2][0], bh[2][1], bh[3][0], bh[3][1],
                  stg + 2 * GT_ROW * 2 + boff + kkb + 16 * GAST * 2);
#pragma unroll
            for (int mi = 0; mi < 4; mi++) {
                unsigned ah[4], al[4];
                ldmx4(ah[0], ah[1], ah[2], ah[3],
                      stg + aoff + kkb + mi * 16 * GAST * 2);
                ldmx4(al[0], al[1], al[2], al[3],
                      stg + GT_ROW * 2 + aoff + kkb + mi * 16 * GAST * 2);
#pragma unroll
                for (int ni = 0; ni < 4; ni++) {
                    mma_f16(d[mi][ni], ah, bh[ni][0], bh[ni][1]);
                    mma_f16(d[mi][ni], al, bh[ni][0], bh[ni][1]);
                }
            }
        }
        __syncthreads();
    }

    // epilogue: Q/K/V hi fp16; V also f32
    const int gid = lane >> 2, tq = lane & 3;
#pragma unroll
    for (int mi = 0; mi < 4; mi++) {
#pragma unroll
        for (int ni = 0; ni < 4; ni++) {
            int gc = col0 + n_base + ni * 8 + tq * 2;
            int which = gc >> 9;
            int hh = (gc >> 6) & 7;
            int dd = gc & 63;
            float sc = (which == 0) ? QK_SCALE : 1.f;
            __half* dh = (which == 0) ? g_Qh : (which == 1) ? g_Kh : g_Vh;
#pragma unroll
            for (int hrow = 0; hrow < 2; hrow++) {
                int m = row0 + m_base + mi * 16 + gid + hrow * 8;
                if (m >= M) continue;
                int bb = m / SEQ, pos = m % SEQ;
                int idx = ((bb * NH + hh) * SEQ + pos) * HD + dd;
                float f0 = d[mi][ni][hrow * 2 + 0] * sc;
                float f1 = d[mi][ni][hrow * 2 + 1] * sc;
                *(unsigned*)(dh + idx) = packh2(__float2half_rn(f0),
                                                __float2half_rn(f1));
                if (which == 2) {
                    float2 v; v.x = f0; v.y = f1;
                    *(float2*)(g_V + idx) = v;
                }
            }
        }
    }
}

// ---------------------------------------------------------------------------
// Fused attention on mma.sync, flash-style (unchanged from R12 passing).
// Q,K,V: fp16 hi; P: fp16 hi. S = qh*kh ; O += ph*vh (1 MMA-set each)
// CTA = 128 threads (4 warps), q-tile 64, k-tile 64, 2-stage cp.async.
// ---------------------------------------------------------------------------
#define ATT_ST 72            // halves per smem row
#define T_ROW (64 * ATT_ST)  // 4608 halves per 64x64 tile
#define STG0_OFF T_ROW
#define STGSZ (2 * T_ROW)    // Kh | Vh

struct TileD { int kor; int vb; int nk; int mode; bool wrap; };
// mode: 0 = STATS (gene keys), 1 = inner-softmax probs, 2 = RAW

__device__ __forceinline__ TileD tdesc(bool is_img, int t) {
    TileD td;
    if (!is_img) {
        td.kor = t * 64;
        td.nk  = (SEQ - td.kor) < 64 ? (SEQ - td.kor) : 64;
        td.vb  = td.kor + NGENE;
        td.mode = 2; td.wrap = true;
    } else if (t < 16) {
        td.kor = NIMG + t * 64; td.nk = 64; td.vb = 0; td.mode = 0; td.wrap = false;
    } else if (t < 32) {
        td.kor = NIMG + (t - 16) * 64; td.nk = 64; td.vb = (t - 16) * 64;
        td.mode = 1; td.wrap = false;
    } else {
        td.kor = (t - 32) * 64;
        td.nk  = (NIMG - td.kor) < 64 ? (NIMG - td.kor) : 64;
        td.vb  = td.kor + NGENE;
        td.mode = 2; td.wrap = false;
    }
    return td;
}

__global__ __launch_bounds__(128)
void attn_mma(float* __restrict__ out)
{
    extern __shared__ __align__(16) __half smh[];
    const int tid = threadIdx.x;
    const int lane = tid & 31, wid = tid >> 5;
    const int tq = lane & 3;
    const int bh = blockIdx.x, qt = blockIdx.y;
    const int bhoff = bh * SEQ * HD;

    const bool is_img = (qt >= 16);
    int qorig0, tbase, nq;
    if (!is_img) { qorig0 = NIMG + qt * 64; tbase = qt * 64; nq = 64; }
    else {
        int i0 = (qt - 16) * 64;
        qorig0 = i0; tbase = NGENE + i0;
        nq = NIMG - i0; if (nq > 64) nq = 64;
    }
    const int ntiles = is_img ? 37 : 21;
    const uint32_t sb = smem_u32(smh);

    // ---- issue Q tile (Qh) via cp.async ----
#pragma unroll
    for (int i = 0; i < 4; i++) {
        int id = tid + i * 128;
        int row = id >> 3, c8 = (id & 7) * 8;
        int tok = qorig0 + (row < nq ? row : nq - 1);
        const __half* src = g_Qh + bhoff + tok * HD + c8;
        uint32_t dst = sb + (row * ATT_ST + c8) * 2;
        CP16(dst, src);
    }
    CP_COMMIT();

    auto issue_kv = [&](int t, int s) {
        TileD td = tdesc(is_img, t);
        uint32_t stg = sb + (STG0_OFF + s * STGSZ) * 2;
#pragma unroll
        for (int i = 0; i < 8; i++) {
            int id = tid + i * 128;
            int arr = id >> 9, rem = id & 511;   // 0 = Kh, 1 = Vh
            int row = rem >> 3, c8 = (rem & 7) * 8;
            int rc = row < td.nk ? row : td.nk - 1;
            const __half* src;
            if (arr == 0) {
                src = g_Kh + bhoff + (td.kor + rc) * HD + c8;
            } else {
                int vi = td.vb + rc;
                if (td.wrap && vi >= SEQ) vi -= SEQ;
                src = g_Vh + bhoff + vi * HD + c8;
            }
            uint32_t dst = stg + (arr * T_ROW + row * ATT_ST + c8) * 2;
            CP16(dst, src);
        }
        CP_COMMIT();
    };

    issue_kv(0, 0);
    CP_WAIT(1);            // Q done (stage0 may be in flight)
    __syncthreads();

    // ---- Q A-fragments (held in regs for the whole kernel) ----
    const int wm = wid;    // warp m-tile
    unsigned qa_h[4][4];
    {
        uint32_t aoff = sb + (((wm * 16 + (lane & 15)) * ATT_ST + (lane >> 4) * 8)) * 2;
#pragma unroll
        for (int c = 0; c < 4; c++)
            ldmx4(qa_h[c][0], qa_h[c][1], qa_h[c][2], qa_h[c][3], aoff + c * 32);
    }

    float O[8][4];
#pragma unroll
    for (int j = 0; j < 8; j++)
#pragma unroll
        for (int c = 0; c < 4; c++) O[j][c] = 0.f;
    float m0 = -INFINITY, m1 = -INFINITY, l0 = 0.f, l1 = 0.f;
    float mg0 = -INFINITY, mg1 = -INFINITY, lg0 = 0.f, lg1 = 0.f;
    float ivl0 = 0.f, ivl1 = 0.f;

    // per-lane ldmatrix address components
    const uint32_t krow = (lane >> 4) * 8 + (lane & 7);       // for K (n-rows)
    const uint32_t ksel = ((lane >> 3) & 1) * 8;              // k halves
    const uint32_t vrow = ((lane >> 3) & 1) * 8 + (lane & 7); // for V (k-rows)
    const uint32_t vcol = (lane >> 4) * 8;

    for (int t = 0; t < ntiles; t++) {
        const int cur = t & 1;
        const bool more = (t + 1 < ntiles);
        TileD td = tdesc(is_img, t);
        if (more) issue_kv(t + 1, cur ^ 1);
        if (more) CP_WAIT(1); else CP_WAIT(0);
        __syncthreads();

        const uint32_t stg = sb + (STG0_OFF + cur * STGSZ) * 2;

        // ---- S = Q K^T (1-term: qh*kh) ----
        float S[8][4];
#pragma unroll
        for (int j = 0; j < 8; j++)
#pragma unroll
            for (int c = 0; c < 4; c++) S[j][c] = 0.f;
#pragma unroll
        for (int jj = 0; jj < 4; jj++) {
            uint32_t rb = (jj * 16 + krow) * ATT_ST;
#pragma unroll
            for (int c = 0; c < 4; c++) {
                uint32_t ad = stg + ((rb + c * 16 + ksel)) * 2;
                unsigned b0, b1, b2, b3;
                ldmx4(b0, b1, b2, b3, ad);                    // Kh
                mma_f16(S[2*jj],   qa_h[c], b0, b1);
                mma_f16(S[2*jj+1], qa_h[c], b2, b3);
            }
        }

        if (td.mode == 0) {
            // inner-softmax stats over gene keys (rows: r0=lane>>2, r1=r0+8)
            float tm0 = -INFINITY, tm1 = -INFINITY;
#pragma unroll
            for (int j = 0; j < 8; j++) {
                tm0 = fmaxf(tm0, fmaxf(S[j][0], S[j][1]));
                tm1 = fmaxf(tm1, fmaxf(S[j][2], S[j][3]));
            }
            tm0 = fmaxf(tm0, __shfl_xor_sync(0xffffffffu, tm0, 1));
            tm0 = fmaxf(tm0, __shfl_xor_sync(0xffffffffu, tm0, 2));
            tm1 = fmaxf(tm1, __shfl_xor_sync(0xffffffffu, tm1, 1));
            tm1 = fmaxf(tm1, __shfl_xor_sync(0xffffffffu, tm1, 2));
            float mn0 = fmaxf(mg0, tm0), mn1 = fmaxf(mg1, tm1);
            float rs0 = 0.f, rs1 = 0.f;
#pragma unroll
            for (int j = 0; j < 8; j++) {
                rs0 += __expf(S[j][0] - mn0) + __expf(S[j][1] - mn0);
                rs1 += __expf(S[j][2] - mn1) + __expf(S[j][3] - mn1);
            }
            rs0 += __shfl_xor_sync(0xffffffffu, rs0, 1);
            rs0 += __shfl_xor_sync(0xffffffffu, rs0, 2);
            rs1 += __shfl_xor_sync(0xffffffffu, rs1, 1);
            rs1 += __shfl_xor_sync(0xffffffffu, rs1, 2);
            lg0 = lg0 * __expf(mg0 - mn0) + rs0; mg0 = mn0;
            lg1 = lg1 * __expf(mg1 - mn1) + rs1; mg1 = mn1;
        } else {
            if (is_img && t == 16) { ivl0 = 1.f / lg0; ivl1 = 1.f / lg1; }
            if (td.mode == 1) {
#pragma unroll
                for (int j = 0; j < 8; j++) {
                    S[j][0] = __expf(S[j][0] - mg0) * ivl0;
                    S[j][1] = __expf(S[j][1] - mg0) * ivl0;
                    S[j][2] = __expf(S[j][2] - mg1) * ivl1;
                    S[j][3] = __expf(S[j][3] - mg1) * ivl1;
                }
            } else if (td.nk < 64) {
#pragma unroll
                for (int j = 0; j < 8; j++) {
                    int c0 = j * 8 + tq * 2;
                    if (c0     >= td.nk) { S[j][0] = -INFINITY; S[j][2] = -INFINITY; }
                    if (c0 + 1 >= td.nk) { S[j][1] = -INFINITY; S[j][3] = -INFINITY; }
                }
            }
            // online softmax
            float tm0 = -INFINITY, tm1 = -INFINITY;
#pragma unroll
            for (int j = 0; j < 8; j++) {
                tm0 = fmaxf(tm0, fmaxf(S[j][0], S[j][1]));
                tm1 = fmaxf(tm1, fmaxf(S[j][2], S[j][3]));
            }
            tm0 = fmaxf(tm0, __shfl_xor_sync(0xffffffffu, tm0, 1));
            tm0 = fmaxf(tm0, __shfl_xor_sync(0xffffffffu, tm0, 2));
            tm1 = fmaxf(tm1, __shfl_xor_sync(0xffffffffu, tm1, 1));
            tm1 = fmaxf(tm1, __shfl_xor_sync(0xffffffffu, tm1, 2));
            float mn0 = fmaxf(m0, tm0), mn1 = fmaxf(m1, tm1);
            float sc0 = __expf(m0 - mn0), sc1 = __expf(m1 - mn1);
            float rs0 = 0.f, rs1 = 0.f;
#pragma unroll
            for (int j = 0; j < 8; j++) {
                S[j][0] = __expf(S[j][0] - mn0); rs0 += S[j][0];
                S[j][1] = __expf(S[j][1] - mn0); rs0 += S[j][1];
                S[j][2] = __expf(S[j][2] - mn1); rs1 += S[j][2];
                S[j][3] = __expf(S[j][3] - mn1); rs1 += S[j][3];
            }
            rs0 += __shfl_xor_sync(0xffffffffu, rs0, 1);
            rs0 += __shfl_xor_sync(0xffffffffu, rs0, 2);
            rs1 += __shfl_xor_sync(0xffffffffu, rs1, 1);
            rs1 += __shfl_xor_sync(0xffffffffu, rs1, 2);
            l0 = l0 * sc0 + rs0; m0 = mn0;
            l1 = l1 * sc1 + rs1; m1 = mn1;
#pragma unroll
            for (int j = 0; j < 8; j++) {
                O[j][0] *= sc0; O[j][1] *= sc0;
                O[j][2] *= sc1; O[j][3] *= sc1;
            }
            // P fragments (A, m16k16): hi only; emitted directly in
            // {a0,a1,a2,a3} = {(r0,k0),(r0+8,k0),(r0,k8),(r0+8,k8)} order.
            unsigned pha[4][4];
#pragma unroll
            for (int kk = 0; kk < 4; kk++) {
#pragma unroll
                for (int q = 0; q < 4; q++) {
                    int j = 2 * kk + (q >> 1);
                    int i0 = (q & 1) ? 2 : 0;
                    pha[kk][q] = packh2(__float2half_rn(S[j][i0]),
                                        __float2half_rn(S[j][i0 + 1]));
                }
            }
            // ---- O += P V (1-term: ph*vh) ----
#pragma unroll
            for (int kk = 0; kk < 4; kk++) {
                uint32_t rb = (kk * 16 + vrow) * ATT_ST + vcol;
#pragma unroll
                for (int dp = 0; dp < 4; dp++) {
                    uint32_t ad = stg + (T_ROW + rb + dp * 16) * 2;
                    unsigned v0, v1, v2, v3;
                    ldmx4t(v0, v1, v2, v3, ad);               // Vh
                    mma_f16(O[2*dp],   pha[kk], v0, v1);
                    mma_f16(O[2*dp+1], pha[kk], v2, v3);
                }
            }
        }
        __syncthreads();
    }

    // ---- epilogue ----
    const int bb = bh >> 3, hh = bh & 7;
    const int r0 = wm * 16 + (lane >> 2), r1 = r0 + 8;
    float inv0 = 1.f / l0, inv1 = 1.f / l1;
#pragma unroll
    for (int dj = 0; dj < 8; dj++) {
        int d0 = dj * 8 + tq * 2;
        if (r0 < nq) {
            float2 o; o.x = O[dj][0] * inv0; o.y = O[dj][1] * inv0;
            *(float2*)(out + ((long)(bb * SEQ + tbase + r0) * (NH * HD)) + hh * HD + d0) = o;
        }
        if (r1 < nq) {
            float2 o; o.x = O[dj][2] * inv1; o.y = O[dj][3] * inv1;
            *(float2*)(out + ((long)(bb * SEQ + tbase + r1) * (NH * HD)) + hh * HD + d0) = o;
        }
    }
}

// ---------------------------------------------------------------------------
// Kernel 3: depthwise conv residual, strips of 8
// ---------------------------------------------------------------------------
#define NSB 42

__global__ __launch_bounds__(256)
void resid_kernel(const float* __restrict__ wres, float* __restrict__ out)
{
    const int blk = blockIdx.x;
    const int sb = blk % NSB;
    const int bh = blk / NSB;
    const int bb = bh >> 3, hh = bh & 7;
    const int dd = threadIdx.x & 63;
    const int s = sb * 4 + (threadIdx.x >> 6);
    const int t0 = s * 8;
    if (t0 >= SEQ) return;

    const float* __restrict__ v = g_V + ((bb * NH + hh) * SEQ) * HD + dd;
    const float* __restrict__ w = wres + hh * KW;

    float win[40];
#pragma unroll
    for (int i = 0; i < 40; i++) {
        int p = t0 - KPAD + i;
        win[i] = (p >= 0 && p < SEQ) ? v[p * HD] : 0.f;
    }
    float o[8];
#pragma unroll
    for (int i = 0; i < 8; i++) o[i] = 0.f;
#pragma unroll
    for (int k = 0; k < KW; k++) {
        float wk = __ldg(w + k);
#pragma unroll
        for (int i = 0; i < 8; i++) o[i] += wk * win[i + k];
    }
#pragma unroll
    for (int i = 0; i < 8; i++) {
        int t = t0 + i;
        if (t < SEQ) {
            int oi = (bb * SEQ + t) * (NH * HD) + hh * HD + dd;
            out[oi] += o[i];
        }
    }
}

// ---------------------------------------------------------------------------
extern "C" void kernel_launch(void* const* d_in, const int* in_sizes, int n_in,
                              void* d_out, int out_size)
{
    const float* x     = (const float*)d_in[0];
    const float* w_qkv = (const float*)d_in[1];
    const float* w_res = (const float*)d_in[2];
    float* out = (float*)d_out;

    const int gemm_smem = 2 * GSTG * 2;                       // 61440 B
    cudaFuncSetAttribute(qkv_gemm_mma, cudaFuncAttributeMaxDynamicSharedMemorySize, gemm_smem);
    const int attn_smem = (T_ROW + 2 * STGSZ) * 2;            // 46080 B
    cudaFuncSetAttribute(attn_mma, cudaFuncAttributeMaxDynamicSharedMemorySize, attn_smem);

    const int xtot = BATCH * SEQ * DIMIN;
    prep_x_kernel<<<(xtot / 4 + 255) / 256, 256>>>(x);

    dim3 gp(NOUTC / 32, DIMIN / 32);
    prep_w_kernel<<<gp, dim3(32, 8)>>>(w_qkv);

    dim3 g1((BATCH * SEQ + 127) / 128, NOUTC / 128);
    qkv_gemm_mma<<<g1, 256, gemm_smem>>>(x);

    dim3 g2(BATCH * NH, 21);
    attn_mma<<<g2, 128, attn_smem>>>(out);

    resid_kernel<<<BATCH * NH * NSB, 256>>>(w_res, out);
}